// round 2
// baseline (speedup 1.0000x reference)
#include <cuda_runtime.h>
#include <math.h>

// Problem constants (fixed by setup_inputs)
#define BB     8
#define SS     2048
#define CC     8
#define DD     9
#define WIN    60
#define NTOT   (BB * SS)      // 16384 windows
#define SIGCH  285            // 9 + 36 + 240
#define H2C    512
#define H1C    256
#define RB     32             // rows per MLP block
#define NW     8              // warps per sig block

// Scratch (static __device__ allocation is allowed)
__device__ float g_feats[NTOT * SIGCH];

// ---------------------------------------------------------------------------
// Lyndon index tables, generated at COMPILE TIME (no setup kernel).
// Tuple lexicographic compare == base-9 integer compare of the encoding.
// ---------------------------------------------------------------------------
struct LyndonTab { short l2[36]; short l3[240]; };
constexpr LyndonTab make_tab() {
    LyndonTab t{};
    int n2 = 0, n3 = 0;
    for (int i = 0; i < DD; i++)
        for (int j = 0; j < DD; j++)
            if (i < j) t.l2[n2++] = (short)(i * 9 + j);
    for (int i = 0; i < DD; i++)
        for (int j = 0; j < DD; j++)
            for (int k = 0; k < DD; k++) {
                int e  = (i * 9 + j) * 9 + k;
                int r1 = (j * 9 + k) * 9 + i;
                int r2 = (k * 9 + i) * 9 + j;
                if (e < r1 && e < r2) t.l3[n3++] = (short)e;
            }
    return t;
}
__constant__ LyndonTab c_tab = make_tab();

// ---------------------------------------------------------------------------
// Kernel A: log-signature features. One warp per window.
// Lanes 0..26: lane owns i = lane/3, j in {3*(lane%3) .. +2}.
// Per-lane state: s1i (S1[i]), S2r[3], S3r[3][9]  -> no cross-lane comm in scan.
// ---------------------------------------------------------------------------
__global__ __launch_bounds__(256) void sig_kernel(const float* __restrict__ x) {
    // vs3 row: first used as increment buffer (60 steps x 12 floats = 720),
    // then reused to hold S3 (729 floats). Row stride 732 floats (2928B, 16B-aligned).
    __shared__ float vs3[NW][732];
    __shared__ float s2s[NW][81];
    __shared__ float s1s[NW][12];

    const int w    = threadIdx.x >> 5;
    const int lane = threadIdx.x & 31;
    const int n    = blockIdx.x * NW + w;
    const int bb   = n >> 11;      // / 2048
    const int ss   = n & 2047;

    float* vbuf = vs3[w];
    const float inv59 = 1.0f / 59.0f;

    // ---- Stage window increments into shared ----
    for (int step = lane; step < WIN; step += 32) {
        int pos  = ss + step - (WIN - 1);
        int posc = pos < 0 ? 0 : pos;
        const float* xr = x + ((size_t)bb * SS + posc) * CC;
        float4 a0 = *(const float4*)(xr);
        float4 a1 = *(const float4*)(xr + 4);
        float vt;
        float4 d0, d1;
        if (step == 0) {
            vt = 0.0f;                 // t[0] = 0, prepend-zero diff -> aug[0]
            d0 = a0; d1 = a1;
        } else {
            vt = inv59;
            int pm  = pos - 1;
            int pmc = pm < 0 ? 0 : pm;
            const float* xp = x + ((size_t)bb * SS + pmc) * CC;
            float4 b0 = *(const float4*)(xp);
            float4 b1 = *(const float4*)(xp + 4);
            d0.x = a0.x - b0.x; d0.y = a0.y - b0.y; d0.z = a0.z - b0.z; d0.w = a0.w - b0.w;
            d1.x = a1.x - b1.x; d1.y = a1.y - b1.y; d1.z = a1.z - b1.z; d1.w = a1.w - b1.w;
        }
        float* vv = vbuf + step * 12;
        vv[0] = vt;
        vv[1] = d0.x; vv[2] = d0.y; vv[3] = d0.z; vv[4] = d0.w;
        vv[5] = d1.x; vv[6] = d1.y; vv[7] = d1.z; vv[8] = d1.w;
    }
    __syncwarp();

    // ---- Chen scan ----
    float S3r[3][9];
    float S2r[3];
    float s1i = 0.0f;
    const int li = lane / 3;
    const int jb = (lane % 3) * 3;

    if (lane < 27) {
#pragma unroll
        for (int c = 0; c < 3; c++) {
            S2r[c] = 0.0f;
#pragma unroll
            for (int k = 0; k < 9; k++) S3r[c][k] = 0.0f;
        }
#pragma unroll 2
        for (int step = 0; step < WIN; step++) {
            const float* vv = vbuf + step * 12;
            float4 va = *(const float4*)(vv);
            float4 vb = *(const float4*)(vv + 4);
            float  v8 = vv[8];
            float  vi = vv[li];                       // LDS broadcast within i-group
            float bcoef = fmaf(vi, 1.0f / 6.0f, 0.5f * s1i);
            float ccoef = fmaf(vi, 0.5f, s1i);
#pragma unroll
            for (int c = 0; c < 3; c++) {
                float vj = vv[jb + c];
                float a = fmaf(bcoef, vj, S2r[c]);    // S2 + (0.5*S1i + vi/6)*vj
                S3r[c][0] = fmaf(a, va.x, S3r[c][0]);
                S3r[c][1] = fmaf(a, va.y, S3r[c][1]);
                S3r[c][2] = fmaf(a, va.z, S3r[c][2]);
                S3r[c][3] = fmaf(a, va.w, S3r[c][3]);
                S3r[c][4] = fmaf(a, vb.x, S3r[c][4]);
                S3r[c][5] = fmaf(a, vb.y, S3r[c][5]);
                S3r[c][6] = fmaf(a, vb.z, S3r[c][6]);
                S3r[c][7] = fmaf(a, vb.w, S3r[c][7]);
                S3r[c][8] = fmaf(a, v8,   S3r[c][8]);
                S2r[c] = fmaf(ccoef, vj, S2r[c]);     // S2 + (S1i + 0.5*vi)*vj
            }
            s1i += vi;
        }
    }
    __syncwarp();

    // ---- Dump state to shared (vs3 row is now free to hold S3) ----
    if (lane < 27) {
#pragma unroll
        for (int c = 0; c < 3; c++) {
            int p = li * 9 + jb + c;
            s2s[w][p] = S2r[c];
#pragma unroll
            for (int k = 0; k < 9; k++) vs3[w][p * 9 + k] = S3r[c][k];
        }
        if ((lane % 3) == 0) s1s[w][li] = s1i;
    }
    __syncwarp();

    // ---- Log-signature + Lyndon gather ----
    const float* S3s = vs3[w];
    const float* S2p = s2s[w];
    const float* S1p = s1s[w];
    float* fo = g_feats + (size_t)n * SIGCH;

    if (lane < 9) fo[lane] = S1p[lane];

    for (int t = lane; t < 36; t += 32) {
        int e = c_tab.l2[t];
        int i = e / 9, j = e % 9;
        fo[9 + t] = S2p[e] - 0.5f * S1p[i] * S1p[j];
    }
    for (int t = lane; t < 240; t += 32) {
        int e  = c_tab.l3[t];
        int k  = e % 9;
        int ij = e / 9;
        int j  = ij % 9;
        int i  = ij / 9;
        float v = S3s[e]
                - 0.5f * (S1p[i] * S2p[j * 9 + k] + S2p[ij] * S1p[k])
                + S1p[i] * S1p[j] * S1p[k] * (1.0f / 3.0f);
        fo[45 + t] = v;
    }
}

// ---------------------------------------------------------------------------
// Packed fp32x2 helpers (FFMA2 — Blackwell packed fp32, PTX-only)
// ---------------------------------------------------------------------------
__device__ __forceinline__ unsigned long long pack2(float lo, float hi) {
    unsigned long long r;
    asm("mov.b64 %0, {%1, %2};" : "=l"(r) : "f"(lo), "f"(hi));
    return r;
}
__device__ __forceinline__ void unpack2(unsigned long long v, float& lo, float& hi) {
    asm("mov.b64 {%0, %1}, %2;" : "=f"(lo), "=f"(hi) : "l"(v));
}
__device__ __forceinline__ void ffma2(unsigned long long& d, unsigned long long a,
                                      unsigned long long b) {
    asm("fma.rn.f32x2 %0, %1, %2, %0;" : "+l"(d) : "l"(a), "l"(b));
}

__device__ __forceinline__ float gelu_exact(float v) {
    return 0.5f * v * (1.0f + erff(v * 0.70710678118654752f));
}

// ---------------------------------------------------------------------------
// Kernel B: fused MLP. 32 rows per 512-thread block (halves weight re-reads
// vs RB=16). Shared k-major tiles with stride 36 floats (144B: 16B-aligned
// rows -> broadcast ulonglong2 loads feed FFMA2 directly).
// ---------------------------------------------------------------------------
#define FS_STRIDE 36
#define HS_STRIDE 36
#define SMEM_MLP  ((SIGCH * FS_STRIDE + H2C * HS_STRIDE + 64) * 4)

__global__ __launch_bounds__(512, 1) void mlp_kernel(
    const float* __restrict__ w1, const float* __restrict__ b1,
    const float* __restrict__ lng, const float* __restrict__ lnb,
    const float* __restrict__ w2, const float* __restrict__ b2,
    float* __restrict__ out)
{
    extern __shared__ float sm[];
    float* fs  = sm;                                 // [285][36] k-major
    float* hs  = sm + SIGCH * FS_STRIDE;             // [512][36] k-major
    float* mus = hs + H2C * HS_STRIDE;               // [32]
    float* rsd = mus + RB;                           // [32]

    const int j    = threadIdx.x;                    // 0..511
    const int row0 = blockIdx.x * RB;
    const float* frow = g_feats + (size_t)row0 * SIGCH;

    // Load 32 feature rows, transposed to k-major (8-way STS conflict, one-time)
    for (int idx = j; idx < RB * SIGCH; idx += 512) {
        int r = idx / SIGCH;
        int k = idx - r * SIGCH;
        fs[k * FS_STRIDE + r] = frow[idx];
    }
    __syncthreads();

    // ---- GEMM1: each thread owns output column j for all 32 rows ----
    unsigned long long acc[16];
#pragma unroll
    for (int p = 0; p < 16; p++) acc[p] = 0ull;

    const float* w1j = w1 + j;
#pragma unroll 2
    for (int k = 0; k < SIGCH; k++) {
        float wv = __ldg(w1j + (size_t)k * H2C);
        unsigned long long wp = pack2(wv, wv);
        const ulonglong2* fp = (const ulonglong2*)(fs + k * FS_STRIDE);
#pragma unroll
        for (int q = 0; q < 8; q++) {
            ulonglong2 f = fp[q];                    // rows 4q..4q+3 at column k
            ffma2(acc[2 * q],     f.x, wp);
            ffma2(acc[2 * q + 1], f.y, wp);
        }
    }

    // ---- bias + exact GELU, store k-major into hs ----
    {
        float bA = b1[j];
        float* hj = hs + j * HS_STRIDE;
#pragma unroll
        for (int p = 0; p < 16; p++) {
            float lo, hi;
            unpack2(acc[p], lo, hi);
            hj[2 * p]     = gelu_exact(lo + bA);
            hj[2 * p + 1] = gelu_exact(hi + bA);
        }
    }
    __syncthreads();

    // ---- LayerNorm stats: warp wid handles rows 2*wid, 2*wid+1 ----
    {
        int wid = j >> 5, lane = j & 31;
#pragma unroll
        for (int rr = 0; rr < 2; rr++) {
            int r = wid * 2 + rr;
            float s = 0.0f, s2 = 0.0f;
            for (int kk = lane; kk < H2C; kk += 32) {
                float h = hs[kk * HS_STRIDE + r];
                s += h;
                s2 = fmaf(h, h, s2);
            }
#pragma unroll
            for (int off = 16; off; off >>= 1) {
                s  += __shfl_down_sync(0xffffffffu, s,  off);
                s2 += __shfl_down_sync(0xffffffffu, s2, off);
            }
            if (lane == 0) {
                float mu  = s * (1.0f / 512.0f);
                float var = s2 * (1.0f / 512.0f) - mu * mu;
                mus[r] = mu;
                rsd[r] = rsqrtf(var + 1e-5f);
            }
        }
    }
    __syncthreads();

    // ---- Normalize in place (thread j owns hs column j) ----
    {
        float g = lng[j], o = lnb[j];
        float* hj = hs + j * HS_STRIDE;
#pragma unroll
        for (int r = 0; r < RB; r++) {
            hj[r] = (hj[r] - mus[r]) * rsd[r] * g + o;
        }
    }
    __syncthreads();

    // ---- GEMM2: 256 cols x 32 rows; thread = (col, row-half) ----
    unsigned long long acc2[8];
#pragma unroll
    for (int p = 0; p < 8; p++) acc2[p] = 0ull;

    const int jc   = j & 255;
    const int half = j >> 8;          // 0: rows 0..15, 1: rows 16..31
    const float* w2j = w2 + jc;
    const float* hb  = hs + half * 16;
#pragma unroll 2
    for (int kk = 0; kk < H2C; kk++) {
        float wv = __ldg(w2j + (size_t)kk * H1C);
        unsigned long long wp = pack2(wv, wv);
        const ulonglong2* hp = (const ulonglong2*)(hb + kk * HS_STRIDE);
#pragma unroll
        for (int q = 0; q < 4; q++) {
            ulonglong2 h = hp[q];
            ffma2(acc2[2 * q],     h.x, wp);
            ffma2(acc2[2 * q + 1], h.y, wp);
        }
    }

    {
        float bo = b2[jc];
        int rbase = row0 + half * 16;
#pragma unroll
        for (int p = 0; p < 8; p++) {
            float lo, hi;
            unpack2(acc2[p], lo, hi);
            out[(size_t)(rbase + 2 * p) * H1C + jc]     = lo + bo;
            out[(size_t)(rbase + 2 * p + 1) * H1C + jc] = hi + bo;
        }
    }
}

// ---------------------------------------------------------------------------
// Launch
// ---------------------------------------------------------------------------
extern "C" void kernel_launch(void* const* d_in, const int* in_sizes, int n_in,
                              void* d_out, int out_size) {
    const float* x   = (const float*)d_in[0];
    const float* w1  = (const float*)d_in[1];
    const float* b1  = (const float*)d_in[2];
    const float* lng = (const float*)d_in[3];
    const float* lnb = (const float*)d_in[4];
    const float* w2  = (const float*)d_in[5];
    const float* b2  = (const float*)d_in[6];
    float* out = (float*)d_out;

    cudaFuncSetAttribute(mlp_kernel, cudaFuncAttributeMaxDynamicSharedMemorySize,
                         SMEM_MLP);

    sig_kernel<<<NTOT / NW, 256>>>(x);
    mlp_kernel<<<NTOT / RB, 512, SMEM_MLP>>>(w1, b1, lng, lnb, w2, b2, out);
}

// round 3
// speedup vs baseline: 1.4063x; 1.4063x over previous
#include <cuda_runtime.h>
#include <math.h>

// Problem constants (fixed by setup_inputs)
#define BB     8
#define SS     2048
#define CC     8
#define DD     9
#define WIN    60
#define NTOT   (BB * SS)      // 16384 windows
#define SIGCH  285            // 9 + 36 + 240
#define H2C    512
#define H1C    256
#define RB     16             // rows per MLP block
#define NW     8              // warps per sig block

// Scratch (static __device__ allocation is allowed)
__device__ float g_feats[NTOT * SIGCH];

// ---------------------------------------------------------------------------
// Lyndon index tables, generated at COMPILE TIME (no setup kernel).
// ---------------------------------------------------------------------------
struct LyndonTab { short l2[36]; short l3[240]; };
constexpr LyndonTab make_tab() {
    LyndonTab t{};
    int n2 = 0, n3 = 0;
    for (int i = 0; i < DD; i++)
        for (int j = 0; j < DD; j++)
            if (i < j) t.l2[n2++] = (short)(i * 9 + j);
    for (int i = 0; i < DD; i++)
        for (int j = 0; j < DD; j++)
            for (int k = 0; k < DD; k++) {
                int e  = (i * 9 + j) * 9 + k;
                int r1 = (j * 9 + k) * 9 + i;
                int r2 = (k * 9 + i) * 9 + j;
                if (e < r1 && e < r2) t.l3[n3++] = (short)e;
            }
    return t;
}
__constant__ LyndonTab c_tab = make_tab();

// ---------------------------------------------------------------------------
// Kernel A: log-signature features. One warp per window.
// ---------------------------------------------------------------------------
__global__ __launch_bounds__(256) void sig_kernel(const float* __restrict__ x) {
    __shared__ float vs3[NW][732];
    __shared__ float s2s[NW][81];
    __shared__ float s1s[NW][12];

    const int w    = threadIdx.x >> 5;
    const int lane = threadIdx.x & 31;
    const int n    = blockIdx.x * NW + w;
    const int bb   = n >> 11;
    const int ss   = n & 2047;

    float* vbuf = vs3[w];
    const float inv59 = 1.0f / 59.0f;

    for (int step = lane; step < WIN; step += 32) {
        int pos  = ss + step - (WIN - 1);
        int posc = pos < 0 ? 0 : pos;
        const float* xr = x + ((size_t)bb * SS + posc) * CC;
        float4 a0 = *(const float4*)(xr);
        float4 a1 = *(const float4*)(xr + 4);
        float vt;
        float4 d0, d1;
        if (step == 0) {
            vt = 0.0f;
            d0 = a0; d1 = a1;
        } else {
            vt = inv59;
            int pm  = pos - 1;
            int pmc = pm < 0 ? 0 : pm;
            const float* xp = x + ((size_t)bb * SS + pmc) * CC;
            float4 b0 = *(const float4*)(xp);
            float4 b1 = *(const float4*)(xp + 4);
            d0.x = a0.x - b0.x; d0.y = a0.y - b0.y; d0.z = a0.z - b0.z; d0.w = a0.w - b0.w;
            d1.x = a1.x - b1.x; d1.y = a1.y - b1.y; d1.z = a1.z - b1.z; d1.w = a1.w - b1.w;
        }
        float* vv = vbuf + step * 12;
        vv[0] = vt;
        vv[1] = d0.x; vv[2] = d0.y; vv[3] = d0.z; vv[4] = d0.w;
        vv[5] = d1.x; vv[6] = d1.y; vv[7] = d1.z; vv[8] = d1.w;
    }
    __syncwarp();

    float S3r[3][9];
    float S2r[3];
    float s1i = 0.0f;
    const int li = lane / 3;
    const int jb = (lane % 3) * 3;

    if (lane < 27) {
#pragma unroll
        for (int c = 0; c < 3; c++) {
            S2r[c] = 0.0f;
#pragma unroll
            for (int k = 0; k < 9; k++) S3r[c][k] = 0.0f;
        }
#pragma unroll 2
        for (int step = 0; step < WIN; step++) {
            const float* vv = vbuf + step * 12;
            float4 va = *(const float4*)(vv);
            float4 vb = *(const float4*)(vv + 4);
            float  v8 = vv[8];
            float  vi = vv[li];
            float bcoef = fmaf(vi, 1.0f / 6.0f, 0.5f * s1i);
            float ccoef = fmaf(vi, 0.5f, s1i);
#pragma unroll
            for (int c = 0; c < 3; c++) {
                float vj = vv[jb + c];
                float a = fmaf(bcoef, vj, S2r[c]);
                S3r[c][0] = fmaf(a, va.x, S3r[c][0]);
                S3r[c][1] = fmaf(a, va.y, S3r[c][1]);
                S3r[c][2] = fmaf(a, va.z, S3r[c][2]);
                S3r[c][3] = fmaf(a, va.w, S3r[c][3]);
                S3r[c][4] = fmaf(a, vb.x, S3r[c][4]);
                S3r[c][5] = fmaf(a, vb.y, S3r[c][5]);
                S3r[c][6] = fmaf(a, vb.z, S3r[c][6]);
                S3r[c][7] = fmaf(a, vb.w, S3r[c][7]);
                S3r[c][8] = fmaf(a, v8,   S3r[c][8]);
                S2r[c] = fmaf(ccoef, vj, S2r[c]);
            }
            s1i += vi;
        }
    }
    __syncwarp();

    if (lane < 27) {
#pragma unroll
        for (int c = 0; c < 3; c++) {
            int p = li * 9 + jb + c;
            s2s[w][p] = S2r[c];
#pragma unroll
            for (int k = 0; k < 9; k++) vs3[w][p * 9 + k] = S3r[c][k];
        }
        if ((lane % 3) == 0) s1s[w][li] = s1i;
    }
    __syncwarp();

    const float* S3s = vs3[w];
    const float* S2p = s2s[w];
    const float* S1p = s1s[w];
    float* fo = g_feats + (size_t)n * SIGCH;

    if (lane < 9) fo[lane] = S1p[lane];

    for (int t = lane; t < 36; t += 32) {
        int e = c_tab.l2[t];
        int i = e / 9, j = e % 9;
        fo[9 + t] = S2p[e] - 0.5f * S1p[i] * S1p[j];
    }
    for (int t = lane; t < 240; t += 32) {
        int e  = c_tab.l3[t];
        int k  = e % 9;
        int ij = e / 9;
        int j  = ij % 9;
        int i  = ij / 9;
        float v = S3s[e]
                - 0.5f * (S1p[i] * S2p[j * 9 + k] + S2p[ij] * S1p[k])
                + S1p[i] * S1p[j] * S1p[k] * (1.0f / 3.0f);
        fo[45 + t] = v;
    }
}

// ---------------------------------------------------------------------------
// Packed fp32x2 helpers (FFMA2)
// ---------------------------------------------------------------------------
__device__ __forceinline__ unsigned long long pack2(float lo, float hi) {
    unsigned long long r;
    asm("mov.b64 %0, {%1, %2};" : "=l"(r) : "f"(lo), "f"(hi));
    return r;
}
__device__ __forceinline__ void unpack2(unsigned long long v, float& lo, float& hi) {
    asm("mov.b64 {%0, %1}, %2;" : "=f"(lo), "=f"(hi) : "l"(v));
}
__device__ __forceinline__ void ffma2(unsigned long long& d, unsigned long long a,
                                      unsigned long long b) {
    asm("fma.rn.f32x2 %0, %1, %2, %0;" : "+l"(d) : "l"(a), "l"(b));
}

__device__ __forceinline__ float gelu_exact(float v) {
    return 0.5f * v * (1.0f + erff(v * 0.70710678118654752f));
}

// ---------------------------------------------------------------------------
// Kernel B: fused MLP. 16 rows per 256-thread block, 2 blocks/SM.
// GEMM1: thread owns adjacent column pair (2j, 2j+1) -> one float2 LDG per k,
// feature LDS shared across both columns (16 FFMA2 per 4 LDS.128).
// GEMM2: thread owns column j (N=256 exactly).
// ---------------------------------------------------------------------------
#define FS_STRIDE 16
#define HS_STRIDE 20
#define SMEM_MLP  ((288 * FS_STRIDE + H2C * HS_STRIDE + 64) * 4)

__global__ __launch_bounds__(256, 2) void mlp_kernel(
    const float* __restrict__ w1, const float* __restrict__ b1,
    const float* __restrict__ lng, const float* __restrict__ lnb,
    const float* __restrict__ w2, const float* __restrict__ b2,
    float* __restrict__ out)
{
    extern __shared__ float sm[];
    float* fs  = sm;                                 // [285][16] k-major
    float* hs  = sm + 288 * FS_STRIDE;               // [512][20] k-major
    float* mus = hs + H2C * HS_STRIDE;               // [16]
    float* rsd = mus + RB;                           // [16]

    const int j    = threadIdx.x;                    // 0..255
    const int row0 = blockIdx.x * RB;
    const float* frow = g_feats + (size_t)row0 * SIGCH;

    // Load 16 feature rows, transposed to k-major
    for (int idx = j; idx < RB * SIGCH; idx += 256) {
        int r = idx / SIGCH;
        int k = idx - r * SIGCH;
        fs[k * FS_STRIDE + r] = frow[idx];
    }
    __syncthreads();

    // ---- GEMM1: columns (2j, 2j+1), 16 rows ----
    unsigned long long a0[8], a1[8];
#pragma unroll
    for (int p = 0; p < 8; p++) { a0[p] = 0ull; a1[p] = 0ull; }

    const float2* w1p = (const float2*)w1 + j;       // +k*256 per k-row
#pragma unroll 8
    for (int k = 0; k < SIGCH; k++) {
        float2 wv = __ldg(w1p + (size_t)k * (H2C / 2));
        unsigned long long p0 = pack2(wv.x, wv.x);
        unsigned long long p1 = pack2(wv.y, wv.y);
        const ulonglong2* fp = (const ulonglong2*)(fs + k * FS_STRIDE);
#pragma unroll
        for (int q = 0; q < 4; q++) {
            ulonglong2 f = fp[q];                    // rows 4q..4q+3 at column k
            ffma2(a0[2 * q],     f.x, p0);
            ffma2(a0[2 * q + 1], f.y, p0);
            ffma2(a1[2 * q],     f.x, p1);
            ffma2(a1[2 * q + 1], f.y, p1);
        }
    }

    // ---- bias + exact GELU, store k-major into hs (cols 2j, 2j+1) ----
    {
        float bA = b1[2 * j], bB = b1[2 * j + 1];
        float* h0 = hs + (2 * j) * HS_STRIDE;
        float* h1 = hs + (2 * j + 1) * HS_STRIDE;
#pragma unroll
        for (int p = 0; p < 8; p++) {
            float lo, hi;
            unpack2(a0[p], lo, hi);
            h0[2 * p]     = gelu_exact(lo + bA);
            h0[2 * p + 1] = gelu_exact(hi + bA);
            unpack2(a1[p], lo, hi);
            h1[2 * p]     = gelu_exact(lo + bB);
            h1[2 * p + 1] = gelu_exact(hi + bB);
        }
    }
    __syncthreads();

    // ---- LayerNorm stats: warp wid handles rows 2*wid, 2*wid+1 ----
    {
        int wid = j >> 5, lane = j & 31;
#pragma unroll
        for (int rr = 0; rr < 2; rr++) {
            int r = wid * 2 + rr;
            float s = 0.0f, s2 = 0.0f;
            for (int kk = lane; kk < H2C; kk += 32) {
                float h = hs[kk * HS_STRIDE + r];
                s += h;
                s2 = fmaf(h, h, s2);
            }
#pragma unroll
            for (int off = 16; off; off >>= 1) {
                s  += __shfl_down_sync(0xffffffffu, s,  off);
                s2 += __shfl_down_sync(0xffffffffu, s2, off);
            }
            if (lane == 0) {
                float mu  = s * (1.0f / 512.0f);
                float var = s2 * (1.0f / 512.0f) - mu * mu;
                mus[r] = mu;
                rsd[r] = rsqrtf(var + 1e-5f);
            }
        }
    }
    __syncthreads();

    // ---- Normalize in place (thread j owns cols 2j, 2j+1) ----
    {
        float g0 = lng[2 * j], g1 = lng[2 * j + 1];
        float o0 = lnb[2 * j], o1 = lnb[2 * j + 1];
        float* h0 = hs + (2 * j) * HS_STRIDE;
        float* h1 = hs + (2 * j + 1) * HS_STRIDE;
#pragma unroll
        for (int r = 0; r < RB; r++) {
            float mu = mus[r], rs = rsd[r];
            h0[r] = (h0[r] - mu) * rs * g0 + o0;
            h1[r] = (h1[r] - mu) * rs * g1 + o1;
        }
    }
    __syncthreads();

    // ---- GEMM2: thread j owns output column j, 16 rows ----
    unsigned long long acc2[8];
#pragma unroll
    for (int p = 0; p < 8; p++) acc2[p] = 0ull;

    const float* w2j = w2 + j;
#pragma unroll 8
    for (int kk = 0; kk < H2C; kk++) {
        float wv = __ldg(w2j + (size_t)kk * H1C);
        unsigned long long wp = pack2(wv, wv);
        const ulonglong2* hp = (const ulonglong2*)(hs + kk * HS_STRIDE);
#pragma unroll
        for (int q = 0; q < 4; q++) {
            ulonglong2 h = hp[q];
            ffma2(acc2[2 * q],     h.x, wp);
            ffma2(acc2[2 * q + 1], h.y, wp);
        }
    }

    {
        float bo = b2[j];
#pragma unroll
        for (int p = 0; p < 8; p++) {
            float lo, hi;
            unpack2(acc2[p], lo, hi);
            out[(size_t)(row0 + 2 * p) * H1C + j]     = lo + bo;
            out[(size_t)(row0 + 2 * p + 1) * H1C + j] = hi + bo;
        }
    }
}

// ---------------------------------------------------------------------------
// Launch
// ---------------------------------------------------------------------------
extern "C" void kernel_launch(void* const* d_in, const int* in_sizes, int n_in,
                              void* d_out, int out_size) {
    const float* x   = (const float*)d_in[0];
    const float* w1  = (const float*)d_in[1];
    const float* b1  = (const float*)d_in[2];
    const float* lng = (const float*)d_in[3];
    const float* lnb = (const float*)d_in[4];
    const float* w2  = (const float*)d_in[5];
    const float* b2  = (const float*)d_in[6];
    float* out = (float*)d_out;

    cudaFuncSetAttribute(mlp_kernel, cudaFuncAttributeMaxDynamicSharedMemorySize,
                         SMEM_MLP);

    sig_kernel<<<NTOT / NW, 256>>>(x);
    mlp_kernel<<<NTOT / RB, 256, SMEM_MLP>>>(w1, b1, lng, lnb, w2, b2, out);
}

// round 4
// speedup vs baseline: 1.4762x; 1.0497x over previous
#include <cuda_runtime.h>
#include <math.h>

// Problem constants (fixed by setup_inputs)
#define BB     8
#define SS     2048
#define CC     8
#define DD     9
#define WIN    60
#define NTOT   (BB * SS)      // 16384 windows
#define SIGCH  285            // 9 + 36 + 240
#define H2C    512
#define H1C    256
#define RB     64             // rows per MLP block
#define NW     8              // warps per sig block

// Scratch (static __device__ allocation is allowed)
__device__ float g_feats[NTOT * SIGCH];

// ---------------------------------------------------------------------------
// Lyndon index tables, generated at COMPILE TIME.
// ---------------------------------------------------------------------------
struct LyndonTab { short l2[36]; short l3[240]; };
constexpr LyndonTab make_tab() {
    LyndonTab t{};
    int n2 = 0, n3 = 0;
    for (int i = 0; i < DD; i++)
        for (int j = 0; j < DD; j++)
            if (i < j) t.l2[n2++] = (short)(i * 9 + j);
    for (int i = 0; i < DD; i++)
        for (int j = 0; j < DD; j++)
            for (int k = 0; k < DD; k++) {
                int e  = (i * 9 + j) * 9 + k;
                int r1 = (j * 9 + k) * 9 + i;
                int r2 = (k * 9 + i) * 9 + j;
                if (e < r1 && e < r2) t.l3[n3++] = (short)e;
            }
    return t;
}
__constant__ LyndonTab c_tab = make_tab();

// ---------------------------------------------------------------------------
// Kernel A: log-signature features. One warp per window. (unchanged)
// ---------------------------------------------------------------------------
__global__ __launch_bounds__(256) void sig_kernel(const float* __restrict__ x) {
    __shared__ float vs3[NW][732];
    __shared__ float s2s[NW][81];
    __shared__ float s1s[NW][12];

    const int w    = threadIdx.x >> 5;
    const int lane = threadIdx.x & 31;
    const int n    = blockIdx.x * NW + w;
    const int bb   = n >> 11;
    const int ss   = n & 2047;

    float* vbuf = vs3[w];
    const float inv59 = 1.0f / 59.0f;

    for (int step = lane; step < WIN; step += 32) {
        int pos  = ss + step - (WIN - 1);
        int posc = pos < 0 ? 0 : pos;
        const float* xr = x + ((size_t)bb * SS + posc) * CC;
        float4 a0 = *(const float4*)(xr);
        float4 a1 = *(const float4*)(xr + 4);
        float vt;
        float4 d0, d1;
        if (step == 0) {
            vt = 0.0f;
            d0 = a0; d1 = a1;
        } else {
            vt = inv59;
            int pm  = pos - 1;
            int pmc = pm < 0 ? 0 : pm;
            const float* xp = x + ((size_t)bb * SS + pmc) * CC;
            float4 b0 = *(const float4*)(xp);
            float4 b1 = *(const float4*)(xp + 4);
            d0.x = a0.x - b0.x; d0.y = a0.y - b0.y; d0.z = a0.z - b0.z; d0.w = a0.w - b0.w;
            d1.x = a1.x - b1.x; d1.y = a1.y - b1.y; d1.z = a1.z - b1.z; d1.w = a1.w - b1.w;
        }
        float* vv = vbuf + step * 12;
        vv[0] = vt;
        vv[1] = d0.x; vv[2] = d0.y; vv[3] = d0.z; vv[4] = d0.w;
        vv[5] = d1.x; vv[6] = d1.y; vv[7] = d1.z; vv[8] = d1.w;
    }
    __syncwarp();

    float S3r[3][9];
    float S2r[3];
    float s1i = 0.0f;
    const int li = lane / 3;
    const int jb = (lane % 3) * 3;

    if (lane < 27) {
#pragma unroll
        for (int c = 0; c < 3; c++) {
            S2r[c] = 0.0f;
#pragma unroll
            for (int k = 0; k < 9; k++) S3r[c][k] = 0.0f;
        }
#pragma unroll 2
        for (int step = 0; step < WIN; step++) {
            const float* vv = vbuf + step * 12;
            float4 va = *(const float4*)(vv);
            float4 vb = *(const float4*)(vv + 4);
            float  v8 = vv[8];
            float  vi = vv[li];
            float bcoef = fmaf(vi, 1.0f / 6.0f, 0.5f * s1i);
            float ccoef = fmaf(vi, 0.5f, s1i);
#pragma unroll
            for (int c = 0; c < 3; c++) {
                float vj = vv[jb + c];
                float a = fmaf(bcoef, vj, S2r[c]);
                S3r[c][0] = fmaf(a, va.x, S3r[c][0]);
                S3r[c][1] = fmaf(a, va.y, S3r[c][1]);
                S3r[c][2] = fmaf(a, va.z, S3r[c][2]);
                S3r[c][3] = fmaf(a, va.w, S3r[c][3]);
                S3r[c][4] = fmaf(a, vb.x, S3r[c][4]);
                S3r[c][5] = fmaf(a, vb.y, S3r[c][5]);
                S3r[c][6] = fmaf(a, vb.z, S3r[c][6]);
                S3r[c][7] = fmaf(a, vb.w, S3r[c][7]);
                S3r[c][8] = fmaf(a, v8,   S3r[c][8]);
                S2r[c] = fmaf(ccoef, vj, S2r[c]);
            }
            s1i += vi;
        }
    }
    __syncwarp();

    if (lane < 27) {
#pragma unroll
        for (int c = 0; c < 3; c++) {
            int p = li * 9 + jb + c;
            s2s[w][p] = S2r[c];
#pragma unroll
            for (int k = 0; k < 9; k++) vs3[w][p * 9 + k] = S3r[c][k];
        }
        if ((lane % 3) == 0) s1s[w][li] = s1i;
    }
    __syncwarp();

    const float* S3s = vs3[w];
    const float* S2p = s2s[w];
    const float* S1p = s1s[w];
    float* fo = g_feats + (size_t)n * SIGCH;

    if (lane < 9) fo[lane] = S1p[lane];

    for (int t = lane; t < 36; t += 32) {
        int e = c_tab.l2[t];
        int i = e / 9, j = e % 9;
        fo[9 + t] = S2p[e] - 0.5f * S1p[i] * S1p[j];
    }
    for (int t = lane; t < 240; t += 32) {
        int e  = c_tab.l3[t];
        int k  = e % 9;
        int ij = e / 9;
        int j  = ij % 9;
        int i  = ij / 9;
        float v = S3s[e]
                - 0.5f * (S1p[i] * S2p[j * 9 + k] + S2p[ij] * S1p[k])
                + S1p[i] * S1p[j] * S1p[k] * (1.0f / 3.0f);
        fo[45 + t] = v;
    }
}

// ---------------------------------------------------------------------------
// Packed fp32x2 helpers (FFMA2)
// ---------------------------------------------------------------------------
__device__ __forceinline__ unsigned long long pack2(float lo, float hi) {
    unsigned long long r;
    asm("mov.b64 %0, {%1, %2};" : "=l"(r) : "f"(lo), "f"(hi));
    return r;
}
__device__ __forceinline__ void unpack2(unsigned long long v, float& lo, float& hi) {
    asm("mov.b64 {%0, %1}, %2;" : "=f"(lo), "=f"(hi) : "l"(v));
}
__device__ __forceinline__ void ffma2(unsigned long long& d, unsigned long long a,
                                      unsigned long long b) {
    asm("fma.rn.f32x2 %0, %1, %2, %0;" : "+l"(d) : "l"(a), "l"(b));
}

__device__ __forceinline__ float gelu_exact(float v) {
    return 0.5f * v * (1.0f + erff(v * 0.70710678118654752f));
}

// ---------------------------------------------------------------------------
// Kernel B: fused MLP. 64 rows per 512-thread block.
// Thread grid: rg = tid/64 (8 row-groups of 8 rows), cg = tid%64.
// GEMM1: thread tile 8 rows x 8 cols. Mainloop LDS is warp-broadcast (all
// lanes of a warp share rg -> same 32B), 32 FFMA2 per 32B LDS.
// LN: stats via shfl reduction; values never leave registers until the single
// normalized store to hs. GEMM2: thread tile 8 rows x 4 cols, broadcast LDS.
// ---------------------------------------------------------------------------
#define FST 68
#define HST 68
#define SMEM_MLP ((SIGCH * FST + H2C * HST) * 4 + 16 * 16 * 4 + 2 * RB * 4 + 64)

__global__ __launch_bounds__(512, 1) void mlp_kernel(
    const float* __restrict__ w1, const float* __restrict__ b1,
    const float* __restrict__ lng, const float* __restrict__ lnb,
    const float* __restrict__ w2, const float* __restrict__ b2,
    float* __restrict__ out)
{
    extern __shared__ float sm[];
    float* fs    = sm;                               // [285][68] k-major
    float* hs    = sm + SIGCH * FST;                 // [512][68] k-major
    float* red_s = hs + H2C * HST;                   // [16 warps][8 rows]
    float* red_q = red_s + 16 * 8;                   // [16 warps][8 rows]
    float* mus   = red_q + 16 * 8;                   // [64]
    float* rsd   = mus + RB;                         // [64]

    const int tid  = threadIdx.x;
    const int rg   = tid >> 6;                       // 0..7
    const int cg   = tid & 63;                       // 0..63
    const int lane = tid & 31;
    const int wid  = tid >> 5;
    const int row0 = blockIdx.x * RB;

    // ---- Stage 64 feature rows into shared, transposed to k-major ----
    {
        const float* frow = g_feats + (size_t)row0 * SIGCH;
        for (int idx = tid; idx < RB * SIGCH; idx += 512) {
            int r = idx / SIGCH;
            int k = idx - r * SIGCH;
            fs[k * FST + r] = frow[idx];
        }
    }
    __syncthreads();

    // ---- GEMM1: rows rg*8..+7, cols cg*8..+7 ----
    unsigned long long acc[4][8];                    // [row-pair][col]
#pragma unroll
    for (int p = 0; p < 4; p++)
#pragma unroll
        for (int c = 0; c < 8; c++) acc[p][c] = 0ull;

    {
        const float4* wbase = (const float4*)(w1 + cg * 8);
        const float*  fbase = fs + rg * 8;
#pragma unroll 4
        for (int k = 0; k < SIGCH; k++) {
            float4 wa = __ldg(wbase + (size_t)k * (H2C / 4));
            float4 wb = __ldg(wbase + (size_t)k * (H2C / 4) + 1);
            ulonglong2 f01 = *(const ulonglong2*)(fbase + k * FST);      // rows 0-3
            ulonglong2 f23 = *(const ulonglong2*)(fbase + k * FST + 4);  // rows 4-7
            float wv[8] = {wa.x, wa.y, wa.z, wa.w, wb.x, wb.y, wb.z, wb.w};
#pragma unroll
            for (int c = 0; c < 8; c++) {
                unsigned long long wp = pack2(wv[c], wv[c]);
                ffma2(acc[0][c], f01.x, wp);
                ffma2(acc[1][c], f01.y, wp);
                ffma2(acc[2][c], f23.x, wp);
                ffma2(acc[3][c], f23.y, wp);
            }
        }
    }

    // ---- bias + exact GELU in registers, accumulate per-row stats ----
    float s1v[8], s2v[8];
#pragma unroll
    for (int r = 0; r < 8; r++) { s1v[r] = 0.0f; s2v[r] = 0.0f; }
    {
        float4 ba = __ldg((const float4*)(b1 + cg * 8));
        float4 bb = __ldg((const float4*)(b1 + cg * 8) + 1);
        float bcol[8] = {ba.x, ba.y, ba.z, ba.w, bb.x, bb.y, bb.z, bb.w};
#pragma unroll
        for (int c = 0; c < 8; c++) {
            float h[8];
            unpack2(acc[0][c], h[0], h[1]);
            unpack2(acc[1][c], h[2], h[3]);
            unpack2(acc[2][c], h[4], h[5]);
            unpack2(acc[3][c], h[6], h[7]);
#pragma unroll
            for (int r = 0; r < 8; r++) {
                h[r] = gelu_exact(h[r] + bcol[c]);
                s1v[r] += h[r];
                s2v[r] = fmaf(h[r], h[r], s2v[r]);
            }
            acc[0][c] = pack2(h[0], h[1]);
            acc[1][c] = pack2(h[2], h[3]);
            acc[2][c] = pack2(h[4], h[5]);
            acc[3][c] = pack2(h[6], h[7]);
        }
    }

    // ---- Row-stat reduction: intra-warp shuffles, then combine 2 warps ----
#pragma unroll
    for (int off = 16; off; off >>= 1) {
#pragma unroll
        for (int r = 0; r < 8; r++) {
            s1v[r] += __shfl_xor_sync(0xffffffffu, s1v[r], off);
            s2v[r] += __shfl_xor_sync(0xffffffffu, s2v[r], off);
        }
    }
    if (lane == 0) {
#pragma unroll
        for (int r = 0; r < 8; r++) {
            red_s[wid * 8 + r] = s1v[r];
            red_q[wid * 8 + r] = s2v[r];
        }
    }
    __syncthreads();
    if (tid < RB) {
        int rgr = tid >> 3, rr = tid & 7;
        float s  = red_s[(2 * rgr) * 8 + rr] + red_s[(2 * rgr + 1) * 8 + rr];
        float q  = red_q[(2 * rgr) * 8 + rr] + red_q[(2 * rgr + 1) * 8 + rr];
        float mu  = s * (1.0f / 512.0f);
        float var = q * (1.0f / 512.0f) - mu * mu;
        mus[tid] = mu;
        rsd[tid] = rsqrtf(var + 1e-5f);
    }
    __syncthreads();

    // ---- Normalize in registers, store hs (k-major) once ----
    {
        float mu_[8], rs_[8];
#pragma unroll
        for (int r = 0; r < 8; r++) { mu_[r] = mus[rg * 8 + r]; rs_[r] = rsd[rg * 8 + r]; }
        float4 ga = __ldg((const float4*)(lng + cg * 8));
        float4 gb = __ldg((const float4*)(lng + cg * 8) + 1);
        float4 oa = __ldg((const float4*)(lnb + cg * 8));
        float4 ob = __ldg((const float4*)(lnb + cg * 8) + 1);
        float gcol[8] = {ga.x, ga.y, ga.z, ga.w, gb.x, gb.y, gb.z, gb.w};
        float ocol[8] = {oa.x, oa.y, oa.z, oa.w, ob.x, ob.y, ob.z, ob.w};
#pragma unroll
        for (int c = 0; c < 8; c++) {
            float h[8];
            unpack2(acc[0][c], h[0], h[1]);
            unpack2(acc[1][c], h[2], h[3]);
            unpack2(acc[2][c], h[4], h[5]);
            unpack2(acc[3][c], h[6], h[7]);
#pragma unroll
            for (int r = 0; r < 8; r++)
                h[r] = fmaf((h[r] - mu_[r]) * rs_[r], gcol[c], ocol[c]);
            float* hcol = hs + (cg * 8 + c) * HST + rg * 8;
            *(float4*)(hcol)     = make_float4(h[0], h[1], h[2], h[3]);
            *(float4*)(hcol + 4) = make_float4(h[4], h[5], h[6], h[7]);
        }
    }
    __syncthreads();

    // ---- GEMM2: rows rg*8..+7, cols cg*4..+3 ----
    unsigned long long acc2[4][4];
#pragma unroll
    for (int p = 0; p < 4; p++)
#pragma unroll
        for (int c = 0; c < 4; c++) acc2[p][c] = 0ull;

    {
        const float4* wbase = (const float4*)(w2 + cg * 4);
        const float*  hbase = hs + rg * 8;
#pragma unroll 4
        for (int k = 0; k < H2C; k++) {
            float4 wv = __ldg(wbase + (size_t)k * (H1C / 4));
            ulonglong2 f01 = *(const ulonglong2*)(hbase + k * HST);
            ulonglong2 f23 = *(const ulonglong2*)(hbase + k * HST + 4);
            float wc[4] = {wv.x, wv.y, wv.z, wv.w};
#pragma unroll
            for (int c = 0; c < 4; c++) {
                unsigned long long wp = pack2(wc[c], wc[c]);
                ffma2(acc2[0][c], f01.x, wp);
                ffma2(acc2[1][c], f01.y, wp);
                ffma2(acc2[2][c], f23.x, wp);
                ffma2(acc2[3][c], f23.y, wp);
            }
        }
    }

    // ---- Epilogue: bias + store ----
    {
        float4 bo = __ldg((const float4*)(b2 + cg * 4));
        float bc[4] = {bo.x, bo.y, bo.z, bo.w};
#pragma unroll
        for (int p = 0; p < 4; p++) {
            float lo[4], hi[4];
#pragma unroll
            for (int c = 0; c < 4; c++) {
                unpack2(acc2[p][c], lo[c], hi[c]);
                lo[c] += bc[c];
                hi[c] += bc[c];
            }
            size_t rA = (size_t)(row0 + rg * 8 + 2 * p) * H1C + cg * 4;
            *(float4*)(out + rA)       = make_float4(lo[0], lo[1], lo[2], lo[3]);
            *(float4*)(out + rA + H1C) = make_float4(hi[0], hi[1], hi[2], hi[3]);
        }
    }
}

// ---------------------------------------------------------------------------
// Launch
// ---------------------------------------------------------------------------
extern "C" void kernel_launch(void* const* d_in, const int* in_sizes, int n_in,
                              void* d_out, int out_size) {
    const float* x   = (const float*)d_in[0];
    const float* w1  = (const float*)d_in[1];
    const float* b1  = (const float*)d_in[2];
    const float* lng = (const float*)d_in[3];
    const float* lnb = (const float*)d_in[4];
    const float* w2  = (const float*)d_in[5];
    const float* b2  = (const float*)d_in[6];
    float* out = (float*)d_out;

    cudaFuncSetAttribute(mlp_kernel, cudaFuncAttributeMaxDynamicSharedMemorySize,
                         SMEM_MLP);

    sig_kernel<<<NTOT / NW, 256>>>(x);
    mlp_kernel<<<NTOT / RB, 512, SMEM_MLP>>>(w1, b1, lng, lnb, w2, b2, out);
}

// round 5
// speedup vs baseline: 1.4764x; 1.0001x over previous
#include <cuda_runtime.h>
#include <math.h>

// Problem constants (fixed by setup_inputs)
#define BB     8
#define SS     2048
#define CC     8
#define DD     9
#define WIN    60
#define NTOT   (BB * SS)      // 16384 windows
#define SIGCH  285            // 9 + 36 + 240
#define H2C    512
#define H1C    256
#define RB     64             // rows per MLP block
#define NW     8              // warps per sig block

// Scratch (static __device__ allocation is allowed)
__device__ float g_feats[NTOT * SIGCH];

// ---------------------------------------------------------------------------
// Lyndon index tables, generated at COMPILE TIME.
// ---------------------------------------------------------------------------
struct LyndonTab { short l2[36]; short l3[240]; };
constexpr LyndonTab make_tab() {
    LyndonTab t{};
    int n2 = 0, n3 = 0;
    for (int i = 0; i < DD; i++)
        for (int j = 0; j < DD; j++)
            if (i < j) t.l2[n2++] = (short)(i * 9 + j);
    for (int i = 0; i < DD; i++)
        for (int j = 0; j < DD; j++)
            for (int k = 0; k < DD; k++) {
                int e  = (i * 9 + j) * 9 + k;
                int r1 = (j * 9 + k) * 9 + i;
                int r2 = (k * 9 + i) * 9 + j;
                if (e < r1 && e < r2) t.l3[n3++] = (short)e;
            }
    return t;
}
__constant__ LyndonTab c_tab = make_tab();

// ---------------------------------------------------------------------------
// Kernel A: log-signature features. One warp per window. (unchanged)
// ---------------------------------------------------------------------------
__global__ __launch_bounds__(256) void sig_kernel(const float* __restrict__ x) {
    __shared__ float vs3[NW][732];
    __shared__ float s2s[NW][81];
    __shared__ float s1s[NW][12];

    const int w    = threadIdx.x >> 5;
    const int lane = threadIdx.x & 31;
    const int n    = blockIdx.x * NW + w;
    const int bb   = n >> 11;
    const int ss   = n & 2047;

    float* vbuf = vs3[w];
    const float inv59 = 1.0f / 59.0f;

    for (int step = lane; step < WIN; step += 32) {
        int pos  = ss + step - (WIN - 1);
        int posc = pos < 0 ? 0 : pos;
        const float* xr = x + ((size_t)bb * SS + posc) * CC;
        float4 a0 = *(const float4*)(xr);
        float4 a1 = *(const float4*)(xr + 4);
        float vt;
        float4 d0, d1;
        if (step == 0) {
            vt = 0.0f;
            d0 = a0; d1 = a1;
        } else {
            vt = inv59;
            int pm  = pos - 1;
            int pmc = pm < 0 ? 0 : pm;
            const float* xp = x + ((size_t)bb * SS + pmc) * CC;
            float4 b0 = *(const float4*)(xp);
            float4 b1 = *(const float4*)(xp + 4);
            d0.x = a0.x - b0.x; d0.y = a0.y - b0.y; d0.z = a0.z - b0.z; d0.w = a0.w - b0.w;
            d1.x = a1.x - b1.x; d1.y = a1.y - b1.y; d1.z = a1.z - b1.z; d1.w = a1.w - b1.w;
        }
        float* vv = vbuf + step * 12;
        vv[0] = vt;
        vv[1] = d0.x; vv[2] = d0.y; vv[3] = d0.z; vv[4] = d0.w;
        vv[5] = d1.x; vv[6] = d1.y; vv[7] = d1.z; vv[8] = d1.w;
    }
    __syncwarp();

    float S3r[3][9];
    float S2r[3];
    float s1i = 0.0f;
    const int li = lane / 3;
    const int jb = (lane % 3) * 3;

    if (lane < 27) {
#pragma unroll
        for (int c = 0; c < 3; c++) {
            S2r[c] = 0.0f;
#pragma unroll
            for (int k = 0; k < 9; k++) S3r[c][k] = 0.0f;
        }
#pragma unroll 2
        for (int step = 0; step < WIN; step++) {
            const float* vv = vbuf + step * 12;
            float4 va = *(const float4*)(vv);
            float4 vb = *(const float4*)(vv + 4);
            float  v8 = vv[8];
            float  vi = vv[li];
            float bcoef = fmaf(vi, 1.0f / 6.0f, 0.5f * s1i);
            float ccoef = fmaf(vi, 0.5f, s1i);
#pragma unroll
            for (int c = 0; c < 3; c++) {
                float vj = vv[jb + c];
                float a = fmaf(bcoef, vj, S2r[c]);
                S3r[c][0] = fmaf(a, va.x, S3r[c][0]);
                S3r[c][1] = fmaf(a, va.y, S3r[c][1]);
                S3r[c][2] = fmaf(a, va.z, S3r[c][2]);
                S3r[c][3] = fmaf(a, va.w, S3r[c][3]);
                S3r[c][4] = fmaf(a, vb.x, S3r[c][4]);
                S3r[c][5] = fmaf(a, vb.y, S3r[c][5]);
                S3r[c][6] = fmaf(a, vb.z, S3r[c][6]);
                S3r[c][7] = fmaf(a, vb.w, S3r[c][7]);
                S3r[c][8] = fmaf(a, v8,   S3r[c][8]);
                S2r[c] = fmaf(ccoef, vj, S2r[c]);
            }
            s1i += vi;
        }
    }
    __syncwarp();

    if (lane < 27) {
#pragma unroll
        for (int c = 0; c < 3; c++) {
            int p = li * 9 + jb + c;
            s2s[w][p] = S2r[c];
#pragma unroll
            for (int k = 0; k < 9; k++) vs3[w][p * 9 + k] = S3r[c][k];
        }
        if ((lane % 3) == 0) s1s[w][li] = s1i;
    }
    __syncwarp();

    const float* S3s = vs3[w];
    const float* S2p = s2s[w];
    const float* S1p = s1s[w];
    float* fo = g_feats + (size_t)n * SIGCH;

    if (lane < 9) fo[lane] = S1p[lane];

    for (int t = lane; t < 36; t += 32) {
        int e = c_tab.l2[t];
        int i = e / 9, j = e % 9;
        fo[9 + t] = S2p[e] - 0.5f * S1p[i] * S1p[j];
    }
    for (int t = lane; t < 240; t += 32) {
        int e  = c_tab.l3[t];
        int k  = e % 9;
        int ij = e / 9;
        int j  = ij % 9;
        int i  = ij / 9;
        float v = S3s[e]
                - 0.5f * (S1p[i] * S2p[j * 9 + k] + S2p[ij] * S1p[k])
                + S1p[i] * S1p[j] * S1p[k] * (1.0f / 3.0f);
        fo[45 + t] = v;
    }
}

// ---------------------------------------------------------------------------
// Packed fp32x2 helpers (FFMA2)
// ---------------------------------------------------------------------------
__device__ __forceinline__ unsigned long long pack2(float lo, float hi) {
    unsigned long long r;
    asm("mov.b64 %0, {%1, %2};" : "=l"(r) : "f"(lo), "f"(hi));
    return r;
}
__device__ __forceinline__ void unpack2(unsigned long long v, float& lo, float& hi) {
    asm("mov.b64 {%0, %1}, %2;" : "=f"(lo), "=f"(hi) : "l"(v));
}
__device__ __forceinline__ void ffma2(unsigned long long& d, unsigned long long a,
                                      unsigned long long b) {
    asm("fma.rn.f32x2 %0, %1, %2, %0;" : "+l"(d) : "l"(a), "l"(b));
}

__device__ __forceinline__ float gelu_exact(float v) {
    return 0.5f * v * (1.0f + erff(v * 0.70710678118654752f));
}

// ---------------------------------------------------------------------------
// Kernel B: fused MLP. 64 rows per 512-thread block.
// Thread grid: rg = tid/64 (8 row-groups of 8 rows), cg = tid%64.
// GEMM1: thread tile 8 rows x 8 cols. Mainloop LDS is warp-broadcast (all
// lanes of a warp share rg -> same 32B), 32 FFMA2 per 32B LDS.
// LN: stats via shfl reduction; values never leave registers until the single
// normalized store to hs. GEMM2: thread tile 8 rows x 4 cols, broadcast LDS.
// ---------------------------------------------------------------------------
#define FST 68
#define HST 68
#define SMEM_MLP ((SIGCH * FST + H2C * HST) * 4 + 16 * 16 * 4 + 2 * RB * 4 + 64)

__global__ __launch_bounds__(512, 1) void mlp_kernel(
    const float* __restrict__ w1, const float* __restrict__ b1,
    const float* __restrict__ lng, const float* __restrict__ lnb,
    const float* __restrict__ w2, const float* __restrict__ b2,
    float* __restrict__ out)
{
    extern __shared__ float sm[];
    float* fs    = sm;                               // [285][68] k-major
    float* hs    = sm + SIGCH * FST;                 // [512][68] k-major
    float* red_s = hs + H2C * HST;                   // [16 warps][8 rows]
    float* red_q = red_s + 16 * 8;                   // [16 warps][8 rows]
    float* mus   = red_q + 16 * 8;                   // [64]
    float* rsd   = mus + RB;                         // [64]

    const int tid  = threadIdx.x;
    const int rg   = tid >> 6;                       // 0..7
    const int cg   = tid & 63;                       // 0..63
    const int lane = tid & 31;
    const int wid  = tid >> 5;
    const int row0 = blockIdx.x * RB;

    // ---- Stage 64 feature rows into shared, transposed to k-major ----
    {
        const float* frow = g_feats + (size_t)row0 * SIGCH;
        for (int idx = tid; idx < RB * SIGCH; idx += 512) {
            int r = idx / SIGCH;
            int k = idx - r * SIGCH;
            fs[k * FST + r] = frow[idx];
        }
    }
    __syncthreads();

    // ---- GEMM1: rows rg*8..+7, cols cg*8..+7 ----
    unsigned long long acc[4][8];                    // [row-pair][col]
#pragma unroll
    for (int p = 0; p < 4; p++)
#pragma unroll
        for (int c = 0; c < 8; c++) acc[p][c] = 0ull;

    {
        const float4* wbase = (const float4*)(w1 + cg * 8);
        const float*  fbase = fs + rg * 8;
#pragma unroll 4
        for (int k = 0; k < SIGCH; k++) {
            float4 wa = __ldg(wbase + (size_t)k * (H2C / 4));
            float4 wb = __ldg(wbase + (size_t)k * (H2C / 4) + 1);
            ulonglong2 f01 = *(const ulonglong2*)(fbase + k * FST);      // rows 0-3
            ulonglong2 f23 = *(const ulonglong2*)(fbase + k * FST + 4);  // rows 4-7
            float wv[8] = {wa.x, wa.y, wa.z, wa.w, wb.x, wb.y, wb.z, wb.w};
#pragma unroll
            for (int c = 0; c < 8; c++) {
                unsigned long long wp = pack2(wv[c], wv[c]);
                ffma2(acc[0][c], f01.x, wp);
                ffma2(acc[1][c], f01.y, wp);
                ffma2(acc[2][c], f23.x, wp);
                ffma2(acc[3][c], f23.y, wp);
            }
        }
    }

    // ---- bias + exact GELU in registers, accumulate per-row stats ----
    float s1v[8], s2v[8];
#pragma unroll
    for (int r = 0; r < 8; r++) { s1v[r] = 0.0f; s2v[r] = 0.0f; }
    {
        float4 ba = __ldg((const float4*)(b1 + cg * 8));
        float4 bb = __ldg((const float4*)(b1 + cg * 8) + 1);
        float bcol[8] = {ba.x, ba.y, ba.z, ba.w, bb.x, bb.y, bb.z, bb.w};
#pragma unroll
        for (int c = 0; c < 8; c++) {
            float h[8];
            unpack2(acc[0][c], h[0], h[1]);
            unpack2(acc[1][c], h[2], h[3]);
            unpack2(acc[2][c], h[4], h[5]);
            unpack2(acc[3][c], h[6], h[7]);
#pragma unroll
            for (int r = 0; r < 8; r++) {
                h[r] = gelu_exact(h[r] + bcol[c]);
                s1v[r] += h[r];
                s2v[r] = fmaf(h[r], h[r], s2v[r]);
            }
            acc[0][c] = pack2(h[0], h[1]);
            acc[1][c] = pack2(h[2], h[3]);
            acc[2][c] = pack2(h[4], h[5]);
            acc[3][c] = pack2(h[6], h[7]);
        }
    }

    // ---- Row-stat reduction: intra-warp shuffles, then combine 2 warps ----
#pragma unroll
    for (int off = 16; off; off >>= 1) {
#pragma unroll
        for (int r = 0; r < 8; r++) {
            s1v[r] += __shfl_xor_sync(0xffffffffu, s1v[r], off);
            s2v[r] += __shfl_xor_sync(0xffffffffu, s2v[r], off);
        }
    }
    if (lane == 0) {
#pragma unroll
        for (int r = 0; r < 8; r++) {
            red_s[wid * 8 + r] = s1v[r];
            red_q[wid * 8 + r] = s2v[r];
        }
    }
    __syncthreads();
    if (tid < RB) {
        int rgr = tid >> 3, rr = tid & 7;
        float s  = red_s[(2 * rgr) * 8 + rr] + red_s[(2 * rgr + 1) * 8 + rr];
        float q  = red_q[(2 * rgr) * 8 + rr] + red_q[(2 * rgr + 1) * 8 + rr];
        float mu  = s * (1.0f / 512.0f);
        float var = q * (1.0f / 512.0f) - mu * mu;
        mus[tid] = mu;
        rsd[tid] = rsqrtf(var + 1e-5f);
    }
    __syncthreads();

    // ---- Normalize in registers, store hs (k-major) once ----
    {
        float mu_[8], rs_[8];
#pragma unroll
        for (int r = 0; r < 8; r++) { mu_[r] = mus[rg * 8 + r]; rs_[r] = rsd[rg * 8 + r]; }
        float4 ga = __ldg((const float4*)(lng + cg * 8));
        float4 gb = __ldg((const float4*)(lng + cg * 8) + 1);
        float4 oa = __ldg((const float4*)(lnb + cg * 8));
        float4 ob = __ldg((const float4*)(lnb + cg * 8) + 1);
        float gcol[8] = {ga.x, ga.y, ga.z, ga.w, gb.x, gb.y, gb.z, gb.w};
        float ocol[8] = {oa.x, oa.y, oa.z, oa.w, ob.x, ob.y, ob.z, ob.w};
#pragma unroll
        for (int c = 0; c < 8; c++) {
            float h[8];
            unpack2(acc[0][c], h[0], h[1]);
            unpack2(acc[1][c], h[2], h[3]);
            unpack2(acc[2][c], h[4], h[5]);
            unpack2(acc[3][c], h[6], h[7]);
#pragma unroll
            for (int r = 0; r < 8; r++)
                h[r] = fmaf((h[r] - mu_[r]) * rs_[r], gcol[c], ocol[c]);
            float* hcol = hs + (cg * 8 + c) * HST + rg * 8;
            *(float4*)(hcol)     = make_float4(h[0], h[1], h[2], h[3]);
            *(float4*)(hcol + 4) = make_float4(h[4], h[5], h[6], h[7]);
        }
    }
    __syncthreads();

    // ---- GEMM2: rows rg*8..+7, cols cg*4..+3 ----
    unsigned long long acc2[4][4];
#pragma unroll
    for (int p = 0; p < 4; p++)
#pragma unroll
        for (int c = 0; c < 4; c++) acc2[p][c] = 0ull;

    {
        const float4* wbase = (const float4*)(w2 + cg * 4);
        const float*  hbase = hs + rg * 8;
#pragma unroll 4
        for (int k = 0; k < H2C; k++) {
            float4 wv = __ldg(wbase + (size_t)k * (H1C / 4));
            ulonglong2 f01 = *(const ulonglong2*)(hbase + k * HST);
            ulonglong2 f23 = *(const ulonglong2*)(hbase + k * HST + 4);
            float wc[4] = {wv.x, wv.y, wv.z, wv.w};
#pragma unroll
            for (int c = 0; c < 4; c++) {
                unsigned long long wp = pack2(wc[c], wc[c]);
                ffma2(acc2[0][c], f01.x, wp);
                ffma2(acc2[1][c], f01.y, wp);
                ffma2(acc2[2][c], f23.x, wp);
                ffma2(acc2[3][c], f23.y, wp);
            }
        }
    }

    // ---- Epilogue: bias + store ----
    {
        float4 bo = __ldg((const float4*)(b2 + cg * 4));
        float bc[4] = {bo.x, bo.y, bo.z, bo.w};
#pragma unroll
        for (int p = 0; p < 4; p++) {
            float lo[4], hi[4];
#pragma unroll
            for (int c = 0; c < 4; c++) {
                unpack2(acc2[p][c], lo[c], hi[c]);
                lo[c] += bc[c];
                hi[c] += bc[c];
            }
            size_t rA = (size_t)(row0 + rg * 8 + 2 * p) * H1C + cg * 4;
            *(float4*)(out + rA)       = make_float4(lo[0], lo[1], lo[2], lo[3]);
            *(float4*)(out + rA + H1C) = make_float4(hi[0], hi[1], hi[2], hi[3]);
        }
    }
}

// ---------------------------------------------------------------------------
// Launch
// ---------------------------------------------------------------------------
extern "C" void kernel_launch(void* const* d_in, const int* in_sizes, int n_in,
                              void* d_out, int out_size) {
    const float* x   = (const float*)d_in[0];
    const float* w1  = (const float*)d_in[1];
    const float* b1  = (const float*)d_in[2];
    const float* lng = (const float*)d_in[3];
    const float* lnb = (const float*)d_in[4];
    const float* w2  = (const float*)d_in[5];
    const float* b2  = (const float*)d_in[6];
    float* out = (float*)d_out;

    cudaFuncSetAttribute(mlp_kernel, cudaFuncAttributeMaxDynamicSharedMemorySize,
                         SMEM_MLP);

    sig_kernel<<<NTOT / NW, 256>>>(x);
    mlp_kernel<<<NTOT / RB, 512, SMEM_MLP>>>(w1, b1, lng, lnb, w2, b2, out);
}

// round 6
// speedup vs baseline: 1.4774x; 1.0007x over previous
#include <cuda_runtime.h>
#include <math.h>

// Problem constants (fixed by setup_inputs)
#define BB     8
#define SS     2048
#define CC     8
#define DD     9
#define WIN    60
#define NTOT   (BB * SS)      // 16384 windows
#define SIGCH  285            // 9 + 36 + 240
#define H2C    512
#define H1C    256
#define RB     64             // rows per MLP block
#define NW     8              // warps per sig block

// Scratch (static __device__ allocation is allowed)
__device__ float g_feats[NTOT * SIGCH];

// ---------------------------------------------------------------------------
// Lyndon index tables, generated at COMPILE TIME.
// ---------------------------------------------------------------------------
struct LyndonTab { short l2[36]; short l3[240]; };
constexpr LyndonTab make_tab() {
    LyndonTab t{};
    int n2 = 0, n3 = 0;
    for (int i = 0; i < DD; i++)
        for (int j = 0; j < DD; j++)
            if (i < j) t.l2[n2++] = (short)(i * 9 + j);
    for (int i = 0; i < DD; i++)
        for (int j = 0; j < DD; j++)
            for (int k = 0; k < DD; k++) {
                int e  = (i * 9 + j) * 9 + k;
                int r1 = (j * 9 + k) * 9 + i;
                int r2 = (k * 9 + i) * 9 + j;
                if (e < r1 && e < r2) t.l3[n3++] = (short)e;
            }
    return t;
}
__constant__ LyndonTab c_tab = make_tab();

// ---------------------------------------------------------------------------
// Kernel A: log-signature features. One warp per window. (unchanged)
// ---------------------------------------------------------------------------
__global__ __launch_bounds__(256) void sig_kernel(const float* __restrict__ x) {
    __shared__ float vs3[NW][732];
    __shared__ float s2s[NW][81];
    __shared__ float s1s[NW][12];

    const int w    = threadIdx.x >> 5;
    const int lane = threadIdx.x & 31;
    const int n    = blockIdx.x * NW + w;
    const int bb   = n >> 11;
    const int ss   = n & 2047;

    float* vbuf = vs3[w];
    const float inv59 = 1.0f / 59.0f;

    for (int step = lane; step < WIN; step += 32) {
        int pos  = ss + step - (WIN - 1);
        int posc = pos < 0 ? 0 : pos;
        const float* xr = x + ((size_t)bb * SS + posc) * CC;
        float4 a0 = *(const float4*)(xr);
        float4 a1 = *(const float4*)(xr + 4);
        float vt;
        float4 d0, d1;
        if (step == 0) {
            vt = 0.0f;
            d0 = a0; d1 = a1;
        } else {
            vt = inv59;
            int pm  = pos - 1;
            int pmc = pm < 0 ? 0 : pm;
            const float* xp = x + ((size_t)bb * SS + pmc) * CC;
            float4 b0 = *(const float4*)(xp);
            float4 b1 = *(const float4*)(xp + 4);
            d0.x = a0.x - b0.x; d0.y = a0.y - b0.y; d0.z = a0.z - b0.z; d0.w = a0.w - b0.w;
            d1.x = a1.x - b1.x; d1.y = a1.y - b1.y; d1.z = a1.z - b1.z; d1.w = a1.w - b1.w;
        }
        float* vv = vbuf + step * 12;
        vv[0] = vt;
        vv[1] = d0.x; vv[2] = d0.y; vv[3] = d0.z; vv[4] = d0.w;
        vv[5] = d1.x; vv[6] = d1.y; vv[7] = d1.z; vv[8] = d1.w;
    }
    __syncwarp();

    float S3r[3][9];
    float S2r[3];
    float s1i = 0.0f;
    const int li = lane / 3;
    const int jb = (lane % 3) * 3;

    if (lane < 27) {
#pragma unroll
        for (int c = 0; c < 3; c++) {
            S2r[c] = 0.0f;
#pragma unroll
            for (int k = 0; k < 9; k++) S3r[c][k] = 0.0f;
        }
#pragma unroll 2
        for (int step = 0; step < WIN; step++) {
            const float* vv = vbuf + step * 12;
            float4 va = *(const float4*)(vv);
            float4 vb = *(const float4*)(vv + 4);
            float  v8 = vv[8];
            float  vi = vv[li];
            float bcoef = fmaf(vi, 1.0f / 6.0f, 0.5f * s1i);
            float ccoef = fmaf(vi, 0.5f, s1i);
#pragma unroll
            for (int c = 0; c < 3; c++) {
                float vj = vv[jb + c];
                float a = fmaf(bcoef, vj, S2r[c]);
                S3r[c][0] = fmaf(a, va.x, S3r[c][0]);
                S3r[c][1] = fmaf(a, va.y, S3r[c][1]);
                S3r[c][2] = fmaf(a, va.z, S3r[c][2]);
                S3r[c][3] = fmaf(a, va.w, S3r[c][3]);
                S3r[c][4] = fmaf(a, vb.x, S3r[c][4]);
                S3r[c][5] = fmaf(a, vb.y, S3r[c][5]);
                S3r[c][6] = fmaf(a, vb.z, S3r[c][6]);
                S3r[c][7] = fmaf(a, vb.w, S3r[c][7]);
                S3r[c][8] = fmaf(a, v8,   S3r[c][8]);
                S2r[c] = fmaf(ccoef, vj, S2r[c]);
            }
            s1i += vi;
        }
    }
    __syncwarp();

    if (lane < 27) {
#pragma unroll
        for (int c = 0; c < 3; c++) {
            int p = li * 9 + jb + c;
            s2s[w][p] = S2r[c];
#pragma unroll
            for (int k = 0; k < 9; k++) vs3[w][p * 9 + k] = S3r[c][k];
        }
        if ((lane % 3) == 0) s1s[w][li] = s1i;
    }
    __syncwarp();

    const float* S3s = vs3[w];
    const float* S2p = s2s[w];
    const float* S1p = s1s[w];
    float* fo = g_feats + (size_t)n * SIGCH;

    if (lane < 9) fo[lane] = S1p[lane];

    for (int t = lane; t < 36; t += 32) {
        int e = c_tab.l2[t];
        int i = e / 9, j = e % 9;
        fo[9 + t] = S2p[e] - 0.5f * S1p[i] * S1p[j];
    }
    for (int t = lane; t < 240; t += 32) {
        int e  = c_tab.l3[t];
        int k  = e % 9;
        int ij = e / 9;
        int j  = ij % 9;
        int i  = ij / 9;
        float v = S3s[e]
                - 0.5f * (S1p[i] * S2p[j * 9 + k] + S2p[ij] * S1p[k])
                + S1p[i] * S1p[j] * S1p[k] * (1.0f / 3.0f);
        fo[45 + t] = v;
    }
}

// ---------------------------------------------------------------------------
// Packed fp32x2 helpers (FFMA2)
// ---------------------------------------------------------------------------
__device__ __forceinline__ unsigned long long pack2(float lo, float hi) {
    unsigned long long r;
    asm("mov.b64 %0, {%1, %2};" : "=l"(r) : "f"(lo), "f"(hi));
    return r;
}
__device__ __forceinline__ void unpack2(unsigned long long v, float& lo, float& hi) {
    asm("mov.b64 {%0, %1}, %2;" : "=f"(lo), "=f"(hi) : "l"(v));
}
__device__ __forceinline__ void ffma2(unsigned long long& d, unsigned long long a,
                                      unsigned long long b) {
    asm("fma.rn.f32x2 %0, %1, %2, %0;" : "+l"(d) : "l"(a), "l"(b));
}

__device__ __forceinline__ float gelu_exact(float v) {
    return 0.5f * v * (1.0f + erff(v * 0.70710678118654752f));
}

// ---------------------------------------------------------------------------
// Kernel B: fused MLP. 64 rows per 512-thread block.
// Thread grid: rg = tid/64 (8 row-groups of 8 rows), cg = tid%64.
// GEMM1: thread tile 8 rows x 8 cols. Mainloop LDS is warp-broadcast (all
// lanes of a warp share rg -> same 32B), 32 FFMA2 per 32B LDS.
// LN: stats via shfl reduction; values never leave registers until the single
// normalized store to hs. GEMM2: thread tile 8 rows x 4 cols, broadcast LDS.
// ---------------------------------------------------------------------------
#define FST 68
#define HST 68
#define SMEM_MLP ((SIGCH * FST + H2C * HST) * 4 + 16 * 16 * 4 + 2 * RB * 4 + 64)

__global__ __launch_bounds__(512, 1) void mlp_kernel(
    const float* __restrict__ w1, const float* __restrict__ b1,
    const float* __restrict__ lng, const float* __restrict__ lnb,
    const float* __restrict__ w2, const float* __restrict__ b2,
    float* __restrict__ out)
{
    extern __shared__ float sm[];
    float* fs    = sm;                               // [285][68] k-major
    float* hs    = sm + SIGCH * FST;                 // [512][68] k-major
    float* red_s = hs + H2C * HST;                   // [16 warps][8 rows]
    float* red_q = red_s + 16 * 8;                   // [16 warps][8 rows]
    float* mus   = red_q + 16 * 8;                   // [64]
    float* rsd   = mus + RB;                         // [64]

    const int tid  = threadIdx.x;
    const int rg   = tid >> 6;                       // 0..7
    const int cg   = tid & 63;                       // 0..63
    const int lane = tid & 31;
    const int wid  = tid >> 5;
    const int row0 = blockIdx.x * RB;

    // ---- Stage 64 feature rows into shared, transposed to k-major ----
    {
        const float* frow = g_feats + (size_t)row0 * SIGCH;
        for (int idx = tid; idx < RB * SIGCH; idx += 512) {
            int r = idx / SIGCH;
            int k = idx - r * SIGCH;
            fs[k * FST + r] = frow[idx];
        }
    }
    __syncthreads();

    // ---- GEMM1: rows rg*8..+7, cols cg*8..+7 ----
    unsigned long long acc[4][8];                    // [row-pair][col]
#pragma unroll
    for (int p = 0; p < 4; p++)
#pragma unroll
        for (int c = 0; c < 8; c++) acc[p][c] = 0ull;

    {
        const float4* wbase = (const float4*)(w1 + cg * 8);
        const float*  fbase = fs + rg * 8;
#pragma unroll 4
        for (int k = 0; k < SIGCH; k++) {
            float4 wa = __ldg(wbase + (size_t)k * (H2C / 4));
            float4 wb = __ldg(wbase + (size_t)k * (H2C / 4) + 1);
            ulonglong2 f01 = *(const ulonglong2*)(fbase + k * FST);      // rows 0-3
            ulonglong2 f23 = *(const ulonglong2*)(fbase + k * FST + 4);  // rows 4-7
            float wv[8] = {wa.x, wa.y, wa.z, wa.w, wb.x, wb.y, wb.z, wb.w};
#pragma unroll
            for (int c = 0; c < 8; c++) {
                unsigned long long wp = pack2(wv[c], wv[c]);
                ffma2(acc[0][c], f01.x, wp);
                ffma2(acc[1][c], f01.y, wp);
                ffma2(acc[2][c], f23.x, wp);
                ffma2(acc[3][c], f23.y, wp);
            }
        }
    }

    // ---- bias + exact GELU in registers, accumulate per-row stats ----
    float s1v[8], s2v[8];
#pragma unroll
    for (int r = 0; r < 8; r++) { s1v[r] = 0.0f; s2v[r] = 0.0f; }
    {
        float4 ba = __ldg((const float4*)(b1 + cg * 8));
        float4 bb = __ldg((const float4*)(b1 + cg * 8) + 1);
        float bcol[8] = {ba.x, ba.y, ba.z, ba.w, bb.x, bb.y, bb.z, bb.w};
#pragma unroll
        for (int c = 0; c < 8; c++) {
            float h[8];
            unpack2(acc[0][c], h[0], h[1]);
            unpack2(acc[1][c], h[2], h[3]);
            unpack2(acc[2][c], h[4], h[5]);
            unpack2(acc[3][c], h[6], h[7]);
#pragma unroll
            for (int r = 0; r < 8; r++) {
                h[r] = gelu_exact(h[r] + bcol[c]);
                s1v[r] += h[r];
                s2v[r] = fmaf(h[r], h[r], s2v[r]);
            }
            acc[0][c] = pack2(h[0], h[1]);
            acc[1][c] = pack2(h[2], h[3]);
            acc[2][c] = pack2(h[4], h[5]);
            acc[3][c] = pack2(h[6], h[7]);
        }
    }

    // ---- Row-stat reduction: intra-warp shuffles, then combine 2 warps ----
#pragma unroll
    for (int off = 16; off; off >>= 1) {
#pragma unroll
        for (int r = 0; r < 8; r++) {
            s1v[r] += __shfl_xor_sync(0xffffffffu, s1v[r], off);
            s2v[r] += __shfl_xor_sync(0xffffffffu, s2v[r], off);
        }
    }
    if (lane == 0) {
#pragma unroll
        for (int r = 0; r < 8; r++) {
            red_s[wid * 8 + r] = s1v[r];
            red_q[wid * 8 + r] = s2v[r];
        }
    }
    __syncthreads();
    if (tid < RB) {
        int rgr = tid >> 3, rr = tid & 7;
        float s  = red_s[(2 * rgr) * 8 + rr] + red_s[(2 * rgr + 1) * 8 + rr];
        float q  = red_q[(2 * rgr) * 8 + rr] + red_q[(2 * rgr + 1) * 8 + rr];
        float mu  = s * (1.0f / 512.0f);
        float var = q * (1.0f / 512.0f) - mu * mu;
        mus[tid] = mu;
        rsd[tid] = rsqrtf(var + 1e-5f);
    }
    __syncthreads();

    // ---- Normalize in registers, store hs (k-major) once ----
    {
        float mu_[8], rs_[8];
#pragma unroll
        for (int r = 0; r < 8; r++) { mu_[r] = mus[rg * 8 + r]; rs_[r] = rsd[rg * 8 + r]; }
        float4 ga = __ldg((const float4*)(lng + cg * 8));
        float4 gb = __ldg((const float4*)(lng + cg * 8) + 1);
        float4 oa = __ldg((const float4*)(lnb + cg * 8));
        float4 ob = __ldg((const float4*)(lnb + cg * 8) + 1);
        float gcol[8] = {ga.x, ga.y, ga.z, ga.w, gb.x, gb.y, gb.z, gb.w};
        float ocol[8] = {oa.x, oa.y, oa.z, oa.w, ob.x, ob.y, ob.z, ob.w};
#pragma unroll
        for (int c = 0; c < 8; c++) {
            float h[8];
            unpack2(acc[0][c], h[0], h[1]);
            unpack2(acc[1][c], h[2], h[3]);
            unpack2(acc[2][c], h[4], h[5]);
            unpack2(acc[3][c], h[6], h[7]);
#pragma unroll
            for (int r = 0; r < 8; r++)
                h[r] = fmaf((h[r] - mu_[r]) * rs_[r], gcol[c], ocol[c]);
            float* hcol = hs + (cg * 8 + c) * HST + rg * 8;
            *(float4*)(hcol)     = make_float4(h[0], h[1], h[2], h[3]);
            *(float4*)(hcol + 4) = make_float4(h[4], h[5], h[6], h[7]);
        }
    }
    __syncthreads();

    // ---- GEMM2: rows rg*8..+7, cols cg*4..+3 ----
    unsigned long long acc2[4][4];
#pragma unroll
    for (int p = 0; p < 4; p++)
#pragma unroll
        for (int c = 0; c < 4; c++) acc2[p][c] = 0ull;

    {
        const float4* wbase = (const float4*)(w2 + cg * 4);
        const float*  hbase = hs + rg * 8;
#pragma unroll 4
        for (int k = 0; k < H2C; k++) {
            float4 wv = __ldg(wbase + (size_t)k * (H1C / 4));
            ulonglong2 f01 = *(const ulonglong2*)(hbase + k * HST);
            ulonglong2 f23 = *(const ulonglong2*)(hbase + k * HST + 4);
            float wc[4] = {wv.x, wv.y, wv.z, wv.w};
#pragma unroll
            for (int c = 0; c < 4; c++) {
                unsigned long long wp = pack2(wc[c], wc[c]);
                ffma2(acc2[0][c], f01.x, wp);
                ffma2(acc2[1][c], f01.y, wp);
                ffma2(acc2[2][c], f23.x, wp);
                ffma2(acc2[3][c], f23.y, wp);
            }
        }
    }

    // ---- Epilogue: bias + store ----
    {
        float4 bo = __ldg((const float4*)(b2 + cg * 4));
        float bc[4] = {bo.x, bo.y, bo.z, bo.w};
#pragma unroll
        for (int p = 0; p < 4; p++) {
            float lo[4], hi[4];
#pragma unroll
            for (int c = 0; c < 4; c++) {
                unpack2(acc2[p][c], lo[c], hi[c]);
                lo[c] += bc[c];
                hi[c] += bc[c];
            }
            size_t rA = (size_t)(row0 + rg * 8 + 2 * p) * H1C + cg * 4;
            *(float4*)(out + rA)       = make_float4(lo[0], lo[1], lo[2], lo[3]);
            *(float4*)(out + rA + H1C) = make_float4(hi[0], hi[1], hi[2], hi[3]);
        }
    }
}

// ---------------------------------------------------------------------------
// Launch
// ---------------------------------------------------------------------------
extern "C" void kernel_launch(void* const* d_in, const int* in_sizes, int n_in,
                              void* d_out, int out_size) {
    const float* x   = (const float*)d_in[0];
    const float* w1  = (const float*)d_in[1];
    const float* b1  = (const float*)d_in[2];
    const float* lng = (const float*)d_in[3];
    const float* lnb = (const float*)d_in[4];
    const float* w2  = (const float*)d_in[5];
    const float* b2  = (const float*)d_in[6];
    float* out = (float*)d_out;

    cudaFuncSetAttribute(mlp_kernel, cudaFuncAttributeMaxDynamicSharedMemorySize,
                         SMEM_MLP);

    sig_kernel<<<NTOT / NW, 256>>>(x);
    mlp_kernel<<<NTOT / RB, 512, SMEM_MLP>>>(w1, b1, lng, lnb, w2, b2, out);
}

// round 7
// speedup vs baseline: 1.4789x; 1.0010x over previous
#include <cuda_runtime.h>
#include <math.h>

// Problem constants (fixed by setup_inputs)
#define BB     8
#define SS     2048
#define CC     8
#define DD     9
#define WIN    60
#define NTOT   (BB * SS)      // 16384 windows
#define SIGCH  285            // 9 + 36 + 240
#define H2C    512
#define H1C    256
#define RB     64             // rows per MLP block
#define NW     8              // warps per sig block

// Scratch (static __device__ allocation is allowed)
__device__ float g_feats[NTOT * SIGCH];

// ---------------------------------------------------------------------------
// Lyndon index tables, generated at COMPILE TIME.
// ---------------------------------------------------------------------------
struct LyndonTab { short l2[36]; short l3[240]; };
constexpr LyndonTab make_tab() {
    LyndonTab t{};
    int n2 = 0, n3 = 0;
    for (int i = 0; i < DD; i++)
        for (int j = 0; j < DD; j++)
            if (i < j) t.l2[n2++] = (short)(i * 9 + j);
    for (int i = 0; i < DD; i++)
        for (int j = 0; j < DD; j++)
            for (int k = 0; k < DD; k++) {
                int e  = (i * 9 + j) * 9 + k;
                int r1 = (j * 9 + k) * 9 + i;
                int r2 = (k * 9 + i) * 9 + j;
                if (e < r1 && e < r2) t.l3[n3++] = (short)e;
            }
    return t;
}
__constant__ LyndonTab c_tab = make_tab();

// ---------------------------------------------------------------------------
// Kernel A: log-signature features. One warp per window. (unchanged)
// ---------------------------------------------------------------------------
__global__ __launch_bounds__(256) void sig_kernel(const float* __restrict__ x) {
    __shared__ float vs3[NW][732];
    __shared__ float s2s[NW][81];
    __shared__ float s1s[NW][12];

    const int w    = threadIdx.x >> 5;
    const int lane = threadIdx.x & 31;
    const int n    = blockIdx.x * NW + w;
    const int bb   = n >> 11;
    const int ss   = n & 2047;

    float* vbuf = vs3[w];
    const float inv59 = 1.0f / 59.0f;

    for (int step = lane; step < WIN; step += 32) {
        int pos  = ss + step - (WIN - 1);
        int posc = pos < 0 ? 0 : pos;
        const float* xr = x + ((size_t)bb * SS + posc) * CC;
        float4 a0 = *(const float4*)(xr);
        float4 a1 = *(const float4*)(xr + 4);
        float vt;
        float4 d0, d1;
        if (step == 0) {
            vt = 0.0f;
            d0 = a0; d1 = a1;
        } else {
            vt = inv59;
            int pm  = pos - 1;
            int pmc = pm < 0 ? 0 : pm;
            const float* xp = x + ((size_t)bb * SS + pmc) * CC;
            float4 b0 = *(const float4*)(xp);
            float4 b1 = *(const float4*)(xp + 4);
            d0.x = a0.x - b0.x; d0.y = a0.y - b0.y; d0.z = a0.z - b0.z; d0.w = a0.w - b0.w;
            d1.x = a1.x - b1.x; d1.y = a1.y - b1.y; d1.z = a1.z - b1.z; d1.w = a1.w - b1.w;
        }
        float* vv = vbuf + step * 12;
        vv[0] = vt;
        vv[1] = d0.x; vv[2] = d0.y; vv[3] = d0.z; vv[4] = d0.w;
        vv[5] = d1.x; vv[6] = d1.y; vv[7] = d1.z; vv[8] = d1.w;
    }
    __syncwarp();

    float S3r[3][9];
    float S2r[3];
    float s1i = 0.0f;
    const int li = lane / 3;
    const int jb = (lane % 3) * 3;

    if (lane < 27) {
#pragma unroll
        for (int c = 0; c < 3; c++) {
            S2r[c] = 0.0f;
#pragma unroll
            for (int k = 0; k < 9; k++) S3r[c][k] = 0.0f;
        }
#pragma unroll 2
        for (int step = 0; step < WIN; step++) {
            const float* vv = vbuf + step * 12;
            float4 va = *(const float4*)(vv);
            float4 vb = *(const float4*)(vv + 4);
            float  v8 = vv[8];
            float  vi = vv[li];
            float bcoef = fmaf(vi, 1.0f / 6.0f, 0.5f * s1i);
            float ccoef = fmaf(vi, 0.5f, s1i);
#pragma unroll
            for (int c = 0; c < 3; c++) {
                float vj = vv[jb + c];
                float a = fmaf(bcoef, vj, S2r[c]);
                S3r[c][0] = fmaf(a, va.x, S3r[c][0]);
                S3r[c][1] = fmaf(a, va.y, S3r[c][1]);
                S3r[c][2] = fmaf(a, va.z, S3r[c][2]);
                S3r[c][3] = fmaf(a, va.w, S3r[c][3]);
                S3r[c][4] = fmaf(a, vb.x, S3r[c][4]);
                S3r[c][5] = fmaf(a, vb.y, S3r[c][5]);
                S3r[c][6] = fmaf(a, vb.z, S3r[c][6]);
                S3r[c][7] = fmaf(a, vb.w, S3r[c][7]);
                S3r[c][8] = fmaf(a, v8,   S3r[c][8]);
                S2r[c] = fmaf(ccoef, vj, S2r[c]);
            }
            s1i += vi;
        }
    }
    __syncwarp();

    if (lane < 27) {
#pragma unroll
        for (int c = 0; c < 3; c++) {
            int p = li * 9 + jb + c;
            s2s[w][p] = S2r[c];
#pragma unroll
            for (int k = 0; k < 9; k++) vs3[w][p * 9 + k] = S3r[c][k];
        }
        if ((lane % 3) == 0) s1s[w][li] = s1i;
    }
    __syncwarp();

    const float* S3s = vs3[w];
    const float* S2p = s2s[w];
    const float* S1p = s1s[w];
    float* fo = g_feats + (size_t)n * SIGCH;

    if (lane < 9) fo[lane] = S1p[lane];

    for (int t = lane; t < 36; t += 32) {
        int e = c_tab.l2[t];
        int i = e / 9, j = e % 9;
        fo[9 + t] = S2p[e] - 0.5f * S1p[i] * S1p[j];
    }
    for (int t = lane; t < 240; t += 32) {
        int e  = c_tab.l3[t];
        int k  = e % 9;
        int ij = e / 9;
        int j  = ij % 9;
        int i  = ij / 9;
        float v = S3s[e]
                - 0.5f * (S1p[i] * S2p[j * 9 + k] + S2p[ij] * S1p[k])
                + S1p[i] * S1p[j] * S1p[k] * (1.0f / 3.0f);
        fo[45 + t] = v;
    }
}

// ---------------------------------------------------------------------------
// Packed fp32x2 helpers (FFMA2)
// ---------------------------------------------------------------------------
__device__ __forceinline__ unsigned long long pack2(float lo, float hi) {
    unsigned long long r;
    asm("mov.b64 %0, {%1, %2};" : "=l"(r) : "f"(lo), "f"(hi));
    return r;
}
__device__ __forceinline__ void unpack2(unsigned long long v, float& lo, float& hi) {
    asm("mov.b64 {%0, %1}, %2;" : "=f"(lo), "=f"(hi) : "l"(v));
}
__device__ __forceinline__ void ffma2(unsigned long long& d, unsigned long long a,
                                      unsigned long long b) {
    asm("fma.rn.f32x2 %0, %1, %2, %0;" : "+l"(d) : "l"(a), "l"(b));
}

__device__ __forceinline__ float gelu_exact(float v) {
    return 0.5f * v * (1.0f + erff(v * 0.70710678118654752f));
}

// ---------------------------------------------------------------------------
// Kernel B: fused MLP. 64 rows per 512-thread block.
// Thread grid: rg = tid/64 (8 row-groups of 8 rows), cg = tid%64.
// GEMM1: thread tile 8 rows x 8 cols. Mainloop LDS is warp-broadcast (all
// lanes of a warp share rg -> same 32B), 32 FFMA2 per 32B LDS.
// LN: stats via shfl reduction; values never leave registers until the single
// normalized store to hs. GEMM2: thread tile 8 rows x 4 cols, broadcast LDS.
// ---------------------------------------------------------------------------
#define FST 68
#define HST 68
#define SMEM_MLP ((SIGCH * FST + H2C * HST) * 4 + 16 * 16 * 4 + 2 * RB * 4 + 64)

__global__ __launch_bounds__(512, 1) void mlp_kernel(
    const float* __restrict__ w1, const float* __restrict__ b1,
    const float* __restrict__ lng, const float* __restrict__ lnb,
    const float* __restrict__ w2, const float* __restrict__ b2,
    float* __restrict__ out)
{
    extern __shared__ float sm[];
    float* fs    = sm;                               // [285][68] k-major
    float* hs    = sm + SIGCH * FST;                 // [512][68] k-major
    float* red_s = hs + H2C * HST;                   // [16 warps][8 rows]
    float* red_q = red_s + 16 * 8;                   // [16 warps][8 rows]
    float* mus   = red_q + 16 * 8;                   // [64]
    float* rsd   = mus + RB;                         // [64]

    const int tid  = threadIdx.x;
    const int rg   = tid >> 6;                       // 0..7
    const int cg   = tid & 63;                       // 0..63
    const int lane = tid & 31;
    const int wid  = tid >> 5;
    const int row0 = blockIdx.x * RB;

    // ---- Stage 64 feature rows into shared, transposed to k-major ----
    {
        const float* frow = g_feats + (size_t)row0 * SIGCH;
        for (int idx = tid; idx < RB * SIGCH; idx += 512) {
            int r = idx / SIGCH;
            int k = idx - r * SIGCH;
            fs[k * FST + r] = frow[idx];
        }
    }
    __syncthreads();

    // ---- GEMM1: rows rg*8..+7, cols cg*8..+7 ----
    unsigned long long acc[4][8];                    // [row-pair][col]
#pragma unroll
    for (int p = 0; p < 4; p++)
#pragma unroll
        for (int c = 0; c < 8; c++) acc[p][c] = 0ull;

    {
        const float4* wbase = (const float4*)(w1 + cg * 8);
        const float*  fbase = fs + rg * 8;
#pragma unroll 4
        for (int k = 0; k < SIGCH; k++) {
            float4 wa = __ldg(wbase + (size_t)k * (H2C / 4));
            float4 wb = __ldg(wbase + (size_t)k * (H2C / 4) + 1);
            ulonglong2 f01 = *(const ulonglong2*)(fbase + k * FST);      // rows 0-3
            ulonglong2 f23 = *(const ulonglong2*)(fbase + k * FST + 4);  // rows 4-7
            float wv[8] = {wa.x, wa.y, wa.z, wa.w, wb.x, wb.y, wb.z, wb.w};
#pragma unroll
            for (int c = 0; c < 8; c++) {
                unsigned long long wp = pack2(wv[c], wv[c]);
                ffma2(acc[0][c], f01.x, wp);
                ffma2(acc[1][c], f01.y, wp);
                ffma2(acc[2][c], f23.x, wp);
                ffma2(acc[3][c], f23.y, wp);
            }
        }
    }

    // ---- bias + exact GELU in registers, accumulate per-row stats ----
    float s1v[8], s2v[8];
#pragma unroll
    for (int r = 0; r < 8; r++) { s1v[r] = 0.0f; s2v[r] = 0.0f; }
    {
        float4 ba = __ldg((const float4*)(b1 + cg * 8));
        float4 bb = __ldg((const float4*)(b1 + cg * 8) + 1);
        float bcol[8] = {ba.x, ba.y, ba.z, ba.w, bb.x, bb.y, bb.z, bb.w};
#pragma unroll
        for (int c = 0; c < 8; c++) {
            float h[8];
            unpack2(acc[0][c], h[0], h[1]);
            unpack2(acc[1][c], h[2], h[3]);
            unpack2(acc[2][c], h[4], h[5]);
            unpack2(acc[3][c], h[6], h[7]);
#pragma unroll
            for (int r = 0; r < 8; r++) {
                h[r] = gelu_exact(h[r] + bcol[c]);
                s1v[r] += h[r];
                s2v[r] = fmaf(h[r], h[r], s2v[r]);
            }
            acc[0][c] = pack2(h[0], h[1]);
            acc[1][c] = pack2(h[2], h[3]);
            acc[2][c] = pack2(h[4], h[5]);
            acc[3][c] = pack2(h[6], h[7]);
        }
    }

    // ---- Row-stat reduction: intra-warp shuffles, then combine 2 warps ----
#pragma unroll
    for (int off = 16; off; off >>= 1) {
#pragma unroll
        for (int r = 0; r < 8; r++) {
            s1v[r] += __shfl_xor_sync(0xffffffffu, s1v[r], off);
            s2v[r] += __shfl_xor_sync(0xffffffffu, s2v[r], off);
        }
    }
    if (lane == 0) {
#pragma unroll
        for (int r = 0; r < 8; r++) {
            red_s[wid * 8 + r] = s1v[r];
            red_q[wid * 8 + r] = s2v[r];
        }
    }
    __syncthreads();
    if (tid < RB) {
        int rgr = tid >> 3, rr = tid & 7;
        float s  = red_s[(2 * rgr) * 8 + rr] + red_s[(2 * rgr + 1) * 8 + rr];
        float q  = red_q[(2 * rgr) * 8 + rr] + red_q[(2 * rgr + 1) * 8 + rr];
        float mu  = s * (1.0f / 512.0f);
        float var = q * (1.0f / 512.0f) - mu * mu;
        mus[tid] = mu;
        rsd[tid] = rsqrtf(var + 1e-5f);
    }
    __syncthreads();

    // ---- Normalize in registers, store hs (k-major) once ----
    {
        float mu_[8], rs_[8];
#pragma unroll
        for (int r = 0; r < 8; r++) { mu_[r] = mus[rg * 8 + r]; rs_[r] = rsd[rg * 8 + r]; }
        float4 ga = __ldg((const float4*)(lng + cg * 8));
        float4 gb = __ldg((const float4*)(lng + cg * 8) + 1);
        float4 oa = __ldg((const float4*)(lnb + cg * 8));
        float4 ob = __ldg((const float4*)(lnb + cg * 8) + 1);
        float gcol[8] = {ga.x, ga.y, ga.z, ga.w, gb.x, gb.y, gb.z, gb.w};
        float ocol[8] = {oa.x, oa.y, oa.z, oa.w, ob.x, ob.y, ob.z, ob.w};
#pragma unroll
        for (int c = 0; c < 8; c++) {
            float h[8];
            unpack2(acc[0][c], h[0], h[1]);
            unpack2(acc[1][c], h[2], h[3]);
            unpack2(acc[2][c], h[4], h[5]);
            unpack2(acc[3][c], h[6], h[7]);
#pragma unroll
            for (int r = 0; r < 8; r++)
                h[r] = fmaf((h[r] - mu_[r]) * rs_[r], gcol[c], ocol[c]);
            float* hcol = hs + (cg * 8 + c) * HST + rg * 8;
            *(float4*)(hcol)     = make_float4(h[0], h[1], h[2], h[3]);
            *(float4*)(hcol + 4) = make_float4(h[4], h[5], h[6], h[7]);
        }
    }
    __syncthreads();

    // ---- GEMM2: rows rg*8..+7, cols cg*4..+3 ----
    unsigned long long acc2[4][4];
#pragma unroll
    for (int p = 0; p < 4; p++)
#pragma unroll
        for (int c = 0; c < 4; c++) acc2[p][c] = 0ull;

    {
        const float4* wbase = (const float4*)(w2 + cg * 4);
        const float*  hbase = hs + rg * 8;
#pragma unroll 4
        for (int k = 0; k < H2C; k++) {
            float4 wv = __ldg(wbase + (size_t)k * (H1C / 4));
            ulonglong2 f01 = *(const ulonglong2*)(hbase + k * HST);
            ulonglong2 f23 = *(const ulonglong2*)(hbase + k * HST + 4);
            float wc[4] = {wv.x, wv.y, wv.z, wv.w};
#pragma unroll
            for (int c = 0; c < 4; c++) {
                unsigned long long wp = pack2(wc[c], wc[c]);
                ffma2(acc2[0][c], f01.x, wp);
                ffma2(acc2[1][c], f01.y, wp);
                ffma2(acc2[2][c], f23.x, wp);
                ffma2(acc2[3][c], f23.y, wp);
            }
        }
    }

    // ---- Epilogue: bias + store ----
    {
        float4 bo = __ldg((const float4*)(b2 + cg * 4));
        float bc[4] = {bo.x, bo.y, bo.z, bo.w};
#pragma unroll
        for (int p = 0; p < 4; p++) {
            float lo[4], hi[4];
#pragma unroll
            for (int c = 0; c < 4; c++) {
                unpack2(acc2[p][c], lo[c], hi[c]);
                lo[c] += bc[c];
                hi[c] += bc[c];
            }
            size_t rA = (size_t)(row0 + rg * 8 + 2 * p) * H1C + cg * 4;
            *(float4*)(out + rA)       = make_float4(lo[0], lo[1], lo[2], lo[3]);
            *(float4*)(out + rA + H1C) = make_float4(hi[0], hi[1], hi[2], hi[3]);
        }
    }
}

// ---------------------------------------------------------------------------
// Launch
// ---------------------------------------------------------------------------
extern "C" void kernel_launch(void* const* d_in, const int* in_sizes, int n_in,
                              void* d_out, int out_size) {
    const float* x   = (const float*)d_in[0];
    const float* w1  = (const float*)d_in[1];
    const float* b1  = (const float*)d_in[2];
    const float* lng = (const float*)d_in[3];
    const float* lnb = (const float*)d_in[4];
    const float* w2  = (const float*)d_in[5];
    const float* b2  = (const float*)d_in[6];
    float* out = (float*)d_out;

    cudaFuncSetAttribute(mlp_kernel, cudaFuncAttributeMaxDynamicSharedMemorySize,
                         SMEM_MLP);

    sig_kernel<<<NTOT / NW, 256>>>(x);
    mlp_kernel<<<NTOT / RB, 512, SMEM_MLP>>>(w1, b1, lng, lnb, w2, b2, out);
}